// round 9
// baseline (speedup 1.0000x reference)
#include <cuda_runtime.h>
#include <cuda_fp16.h>
#include <cstddef>
#include <cstdint>

#define VOCAB 100000
#define NB    16384
#define LSEQ  200
#define EMB   128
#define NCLS  1000

// Scratch (alloc-free rule: __device__ globals).
__device__ __align__(16) __half g_table_h[(size_t)VOCAB * EMB];   // 25.6 MB
__device__ __align__(16) __half g_w_h[(size_t)NCLS * EMB];        // 256 KB
__device__ __align__(16) __half g_pooled_h[(size_t)NB * EMB];     // 4 MB

// ---------------------------------------------------------------------------
// Stage 0: convert table AND fc_w fp32 -> fp16 — EXACT R4/R7 version
// (proven 12.2 us; MLP_p1 = 4, regs 28, occ ~76%).
// ---------------------------------------------------------------------------
#define N_TBL4 ((size_t)VOCAB * EMB / 4)   // 3,200,000 float4
#define N_W4   ((size_t)NCLS * EMB / 4)    //    32,000 float4
#define N_ALL4 (N_TBL4 + N_W4)

__global__ __launch_bounds__(256) void convert_kernel(const float* __restrict__ t,
                                                      const float* __restrict__ W) {
    const size_t base = (size_t)blockIdx.x * 1024 + threadIdx.x;
    float4 v[4];
    bool   ok[4];
    #pragma unroll
    for (int i = 0; i < 4; ++i) {
        const size_t idx = base + (size_t)i * 256;
        ok[i] = idx < N_ALL4;
        if (ok[i])
            v[i] = (idx < N_TBL4) ? reinterpret_cast<const float4*>(t)[idx]
                                  : reinterpret_cast<const float4*>(W)[idx - N_TBL4];
    }
    #pragma unroll
    for (int i = 0; i < 4; ++i) {
        if (!ok[i]) continue;
        const size_t idx = base + (size_t)i * 256;
        union { __half2 h[2]; uint2 u; } pk;
        pk.h[0] = __floats2half2_rn(v[i].x, v[i].y);
        pk.h[1] = __floats2half2_rn(v[i].z, v[i].w);
        if (idx < N_TBL4) reinterpret_cast<uint2*>(g_table_h)[idx] = pk.u;
        else              reinterpret_cast<uint2*>(g_w_h)[idx - N_TBL4] = pk.u;
    }
}

// ---------------------------------------------------------------------------
// Stage 1: masked embedding-bag sum pool — EXACT R3 version (at the LTS cap).
// ---------------------------------------------------------------------------
__device__ __forceinline__ void hacc(float4& a, uint2 u) {
    const float2 f0 = __half22float2(*reinterpret_cast<__half2*>(&u.x));
    const float2 f1 = __half22float2(*reinterpret_cast<__half2*>(&u.y));
    a.x += f0.x; a.y += f0.y; a.z += f1.x; a.w += f1.y;
}

__global__ __launch_bounds__(256) void pool_kernel(const int* __restrict__ seq) {
    __shared__ int s_tok[8][LSEQ];
    const int wid  = threadIdx.x >> 5;
    const int lane = threadIdx.x & 31;
    const int b0   = blockIdx.x * 8;

    for (int i = threadIdx.x; i < 8 * LSEQ; i += 256)
        s_tok[i / LSEQ][i % LSEQ] = seq[(size_t)b0 * LSEQ + i];
    __syncthreads();

    float4 a0 = {0,0,0,0}, a1 = {0,0,0,0}, a2 = {0,0,0,0}, a3 = {0,0,0,0};

    #pragma unroll 2
    for (int l = 0; l < LSEQ; l += 4) {
        const int t0 = s_tok[wid][l + 0];
        const int t1 = s_tok[wid][l + 1];
        const int t2 = s_tok[wid][l + 2];
        const int t3 = s_tok[wid][l + 3];
        if (t0) hacc(a0, reinterpret_cast<const uint2*>(g_table_h + (size_t)t0 * EMB)[lane]);
        if (t1) hacc(a1, reinterpret_cast<const uint2*>(g_table_h + (size_t)t1 * EMB)[lane]);
        if (t2) hacc(a2, reinterpret_cast<const uint2*>(g_table_h + (size_t)t2 * EMB)[lane]);
        if (t3) hacc(a3, reinterpret_cast<const uint2*>(g_table_h + (size_t)t3 * EMB)[lane]);
    }

    union { __half2 h[2]; uint2 u; } pk;
    pk.h[0] = __floats2half2_rn((a0.x + a1.x) + (a2.x + a3.x),
                                (a0.y + a1.y) + (a2.y + a3.y));
    pk.h[1] = __floats2half2_rn((a0.z + a1.z) + (a2.z + a3.z),
                                (a0.w + a1.w) + (a2.w + a3.w));
    reinterpret_cast<uint2*>(g_pooled_h + (size_t)(b0 + wid) * EMB)[lane] = pk.u;
}

// ---------------------------------------------------------------------------
// Stage 2: persistent-A HMMA GEMM. Grid = 128 m-blocks; each block loads its
// 128x128 A tile ONCE (A L2 traffic 32MB -> 4MB), then loops 16 n-passes of
// 64 with register-prefetched B (load for pass p+1 in flight during pass p's
// mma+epilogue). Inner mma/epilogue identical to the proven R7 code.
// ---------------------------------------------------------------------------
__device__ __forceinline__ void mma16816(float* d,
                                         uint32_t a0, uint32_t a1, uint32_t a2, uint32_t a3,
                                         uint32_t b0, uint32_t b1) {
    asm volatile(
        "mma.sync.aligned.m16n8k16.row.col.f32.f16.f16.f32 "
        "{%0,%1,%2,%3}, {%4,%5,%6,%7}, {%8,%9}, {%0,%1,%2,%3};\n"
        : "+f"(d[0]), "+f"(d[1]), "+f"(d[2]), "+f"(d[3])
        : "r"(a0), "r"(a1), "r"(a2), "r"(a3), "r"(b0), "r"(b1));
}

__device__ __forceinline__ int swz(int row, int chunk) {
    return row * 128 + ((chunk ^ (row & 7)) << 3);
}

#define GEMM_NPASS 16   // 16 x 64 = 1024 >= NCLS

__global__ __launch_bounds__(256) void gemm_kernel(const float* __restrict__ bias,
                                                   float* __restrict__ out) {
    __shared__ __half sA[128 * 128];   // 32 KB, loaded once
    __shared__ __half sB[64 * 128];    // 16 KB, rewritten every pass

    const int tid  = threadIdx.x;
    const int lane = tid & 31;
    const int wid  = tid >> 5;
    const int wm   = wid >> 1;         // 0..3 (m, 32 rows each)
    const int wn   = wid & 1;          // 0..1 (n, 32 cols each)
    const int m0   = blockIdx.x * 128;

    const int lq = lane >> 2;
    const int lr = lane & 3;
    const int r0 = tid >> 4;           // 0..15 (loader row)
    const int c  = tid & 15;           // loader chunk

    // Load A tile once: 128 rows x 16 chunks.
    #pragma unroll
    for (int it = 0; it < 8; ++it) {
        const int r = r0 + it * 16;
        const uint4 v = reinterpret_cast<const uint4*>(
            g_pooled_h + (size_t)(m0 + r) * EMB)[c];
        *reinterpret_cast<uint4*>(&sA[swz(r, c)]) = v;
    }

    // Preload B for pass 0 into registers.
    uint4 vb[4];
    #pragma unroll
    for (int it = 0; it < 4; ++it) {
        const int r = r0 + it * 16;
        vb[it] = (r < NCLS)   // pass 0: n0 = 0
            ? reinterpret_cast<const uint4*>(g_w_h + (size_t)r * EMB)[c]
            : make_uint4(0u, 0u, 0u, 0u);
    }

    #pragma unroll 2
    for (int p = 0; p < GEMM_NPASS; ++p) {
        const int n0 = p * 64;

        // (a) all warps done reading sB from the previous pass
        //     (also orders the one-time sA stores before the first mma).
        __syncthreads();

        // Commit this pass's B to smem.
        #pragma unroll
        for (int it = 0; it < 4; ++it)
            *reinterpret_cast<uint4*>(&sB[swz(r0 + it * 16, c)]) = vb[it];

        // Prefetch next pass's B — in flight during mma + epilogue.
        uint4 vb2[4];
        if (p + 1 < GEMM_NPASS) {
            const int n1 = (p + 1) * 64;
            #pragma unroll
            for (int it = 0; it < 4; ++it) {
                const int r = r0 + it * 16;
                vb2[it] = (n1 + r < NCLS)
                    ? reinterpret_cast<const uint4*>(g_w_h + (size_t)(n1 + r) * EMB)[c]
                    : make_uint4(0u, 0u, 0u, 0u);
            }
        }

        // (b) sB visible to all warps.
        __syncthreads();

        float acc[2][4][4] = {};

        #pragma unroll
        for (int ks = 0; ks < 8; ++ks) {
            uint32_t a[2][4];
            #pragma unroll
            for (int mi = 0; mi < 2; ++mi) {
                const int r  = wm * 32 + mi * 16 + lq;
                const int o0 = ((2 * ks)     ^ (r & 7)) * 8 + lr * 2;
                const int o1 = ((2 * ks + 1) ^ (r & 7)) * 8 + lr * 2;
                a[mi][0] = *reinterpret_cast<const uint32_t*>(&sA[r * 128 + o0]);
                a[mi][1] = *reinterpret_cast<const uint32_t*>(&sA[(r + 8) * 128 + o0]);
                a[mi][2] = *reinterpret_cast<const uint32_t*>(&sA[r * 128 + o1]);
                a[mi][3] = *reinterpret_cast<const uint32_t*>(&sA[(r + 8) * 128 + o1]);
            }
            #pragma unroll
            for (int nt = 0; nt < 4; ++nt) {
                const int n  = wn * 32 + nt * 8 + lq;
                const int o0 = ((2 * ks)     ^ (n & 7)) * 8 + lr * 2;
                const int o1 = ((2 * ks + 1) ^ (n & 7)) * 8 + lr * 2;
                const uint32_t b0 = *reinterpret_cast<const uint32_t*>(&sB[n * 128 + o0]);
                const uint32_t b1 = *reinterpret_cast<const uint32_t*>(&sB[n * 128 + o1]);
                #pragma unroll
                for (int mi = 0; mi < 2; ++mi)
                    mma16816(acc[mi][nt], a[mi][0], a[mi][1], a[mi][2], a[mi][3], b0, b1);
            }
        }

        // Epilogue: fused bias, predicated float2 stores.
        #pragma unroll
        for (int nt = 0; nt < 4; ++nt) {
            const int n = n0 + wn * 32 + nt * 8 + lr * 2;
            if (n < NCLS) {
                const float2 b2 = *reinterpret_cast<const float2*>(bias + n);
                #pragma unroll
                for (int mi = 0; mi < 2; ++mi) {
                    const int m = m0 + wm * 32 + mi * 16 + lq;
                    float2 s0, s1;
                    s0.x = acc[mi][nt][0] + b2.x;
                    s0.y = acc[mi][nt][1] + b2.y;
                    s1.x = acc[mi][nt][2] + b2.x;
                    s1.y = acc[mi][nt][3] + b2.y;
                    *reinterpret_cast<float2*>(out + (size_t)m * NCLS + n)       = s0;
                    *reinterpret_cast<float2*>(out + (size_t)(m + 8) * NCLS + n) = s1;
                }
            }
        }

        #pragma unroll
        for (int it = 0; it < 4; ++it) vb[it] = vb2[it];
    }
}

extern "C" void kernel_launch(void* const* d_in, const int* in_sizes, int n_in,
                              void* d_out, int out_size) {
    const int*   seq   = (const int*)d_in[0];
    const float* table = (const float*)d_in[1];
    const float* W     = (const float*)d_in[2];
    const float* bias  = (const float*)d_in[3];
    float*       out   = (float*)d_out;

    const int conv_blocks = (int)((N_ALL4 + 1023) / 1024);
    convert_kernel<<<conv_blocks, 256>>>(table, W);

    pool_kernel<<<NB / 8, 256>>>(seq);

    gemm_kernel<<<NB / 128, 256>>>(bias, out);
}

// round 10
// speedup vs baseline: 1.0269x; 1.0269x over previous
#include <cuda_runtime.h>
#include <cuda_fp16.h>
#include <cstddef>
#include <cstdint>

#define VOCAB 100000
#define NB    16384
#define LSEQ  200
#define EMB   128
#define NCLS  1000

// Scratch (alloc-free rule: __device__ globals).
__device__ __align__(16) __half g_table_h[(size_t)VOCAB * EMB];   // 25.6 MB
__device__ __align__(16) __half g_w_h[(size_t)NCLS * EMB];        // 256 KB
__device__ __align__(16) __half g_pooled_h[(size_t)NB * EMB];     // 4 MB

// ---------------------------------------------------------------------------
// Stage 0: convert table AND fc_w fp32 -> fp16 — proven R4/R7 version.
// ---------------------------------------------------------------------------
#define N_TBL4 ((size_t)VOCAB * EMB / 4)
#define N_W4   ((size_t)NCLS * EMB / 4)
#define N_ALL4 (N_TBL4 + N_W4)

__global__ __launch_bounds__(256) void convert_kernel(const float* __restrict__ t,
                                                      const float* __restrict__ W) {
    const size_t base = (size_t)blockIdx.x * 1024 + threadIdx.x;
    float4 v[4];
    bool   ok[4];
    #pragma unroll
    for (int i = 0; i < 4; ++i) {
        const size_t idx = base + (size_t)i * 256;
        ok[i] = idx < N_ALL4;
        if (ok[i])
            v[i] = (idx < N_TBL4) ? reinterpret_cast<const float4*>(t)[idx]
                                  : reinterpret_cast<const float4*>(W)[idx - N_TBL4];
    }
    #pragma unroll
    for (int i = 0; i < 4; ++i) {
        if (!ok[i]) continue;
        const size_t idx = base + (size_t)i * 256;
        union { __half2 h[2]; uint2 u; } pk;
        pk.h[0] = __floats2half2_rn(v[i].x, v[i].y);
        pk.h[1] = __floats2half2_rn(v[i].z, v[i].w);
        if (idx < N_TBL4) reinterpret_cast<uint2*>(g_table_h)[idx] = pk.u;
        else              reinterpret_cast<uint2*>(g_w_h)[idx - N_TBL4] = pk.u;
    }
}

// ---------------------------------------------------------------------------
// Stage 1: pool with LDG.128 — TWO tokens per warp-load.
// One warp per batch row. Lane j serves token (pair + j>>4) at 16B chunk
// (j&15): each half-warp reads one full 256B fp16 row, so one LDG.128
// covers two tokens. 4 independent load slots (2KB in flight per warp).
// Cross-half combine via shfl.xor(16) at the end.
// ---------------------------------------------------------------------------
__device__ __forceinline__ void hacc8(float4& a, float4& b, uint4 u) {
    const float2 f0 = __half22float2(*reinterpret_cast<__half2*>(&u.x));
    const float2 f1 = __half22float2(*reinterpret_cast<__half2*>(&u.y));
    const float2 f2 = __half22float2(*reinterpret_cast<__half2*>(&u.z));
    const float2 f3 = __half22float2(*reinterpret_cast<__half2*>(&u.w));
    a.x += f0.x; a.y += f0.y; a.z += f1.x; a.w += f1.y;
    b.x += f2.x; b.y += f2.y; b.z += f3.x; b.w += f3.y;
}

__global__ __launch_bounds__(256) void pool_kernel(const int* __restrict__ seq) {
    __shared__ int s_tok[8][LSEQ];
    const int wid  = threadIdx.x >> 5;
    const int lane = threadIdx.x & 31;
    const int b0   = blockIdx.x * 8;

    for (int i = threadIdx.x; i < 8 * LSEQ; i += 256)
        s_tok[i / LSEQ][i % LSEQ] = seq[(size_t)b0 * LSEQ + i];
    __syncthreads();

    const int half = lane >> 4;    // which token of the pair
    const int c    = lane & 15;    // 16B chunk within the 256B row

    float4 accA[4], accB[4];
    #pragma unroll
    for (int i = 0; i < 4; ++i) {
        accA[i] = make_float4(0.f, 0.f, 0.f, 0.f);
        accB[i] = make_float4(0.f, 0.f, 0.f, 0.f);
    }

    for (int l = 0; l < LSEQ; l += 8) {   // 200 % 8 == 0; 4 LDG.128 per iter
        int  tok[4];
        uint4 v[4];
        #pragma unroll
        for (int i = 0; i < 4; ++i) tok[i] = s_tok[wid][l + 2 * i + half];
        #pragma unroll
        for (int i = 0; i < 4; ++i)
            if (tok[i])
                v[i] = *reinterpret_cast<const uint4*>(
                    g_table_h + (size_t)tok[i] * EMB + c * 8);
        #pragma unroll
        for (int i = 0; i < 4; ++i)
            if (tok[i]) hacc8(accA[i], accB[i], v[i]);
    }

    float r[8];
    r[0] = (accA[0].x + accA[1].x) + (accA[2].x + accA[3].x);
    r[1] = (accA[0].y + accA[1].y) + (accA[2].y + accA[3].y);
    r[2] = (accA[0].z + accA[1].z) + (accA[2].z + accA[3].z);
    r[3] = (accA[0].w + accA[1].w) + (accA[2].w + accA[3].w);
    r[4] = (accB[0].x + accB[1].x) + (accB[2].x + accB[3].x);
    r[5] = (accB[0].y + accB[1].y) + (accB[2].y + accB[3].y);
    r[6] = (accB[0].z + accB[1].z) + (accB[2].z + accB[3].z);
    r[7] = (accB[0].w + accB[1].w) + (accB[2].w + accB[3].w);

    // Combine the even-token half with the odd-token half.
    #pragma unroll
    for (int i = 0; i < 8; ++i)
        r[i] += __shfl_xor_sync(0xffffffffu, r[i], 16);

    if (half == 0) {
        union { __half2 h[4]; uint4 u; } pk;
        pk.h[0] = __floats2half2_rn(r[0], r[1]);
        pk.h[1] = __floats2half2_rn(r[2], r[3]);
        pk.h[2] = __floats2half2_rn(r[4], r[5]);
        pk.h[3] = __floats2half2_rn(r[6], r[7]);
        *reinterpret_cast<uint4*>(
            g_pooled_h + (size_t)(b0 + wid) * EMB + c * 8) = pk.u;
    }
}

// ---------------------------------------------------------------------------
// Stage 2: HMMA GEMM — EXACT R7 version (tied-best, lowest L2 pressure).
// ---------------------------------------------------------------------------
__device__ __forceinline__ void mma16816(float* d,
                                         uint32_t a0, uint32_t a1, uint32_t a2, uint32_t a3,
                                         uint32_t b0, uint32_t b1) {
    asm volatile(
        "mma.sync.aligned.m16n8k16.row.col.f32.f16.f16.f32 "
        "{%0,%1,%2,%3}, {%4,%5,%6,%7}, {%8,%9}, {%0,%1,%2,%3};\n"
        : "+f"(d[0]), "+f"(d[1]), "+f"(d[2]), "+f"(d[3])
        : "r"(a0), "r"(a1), "r"(a2), "r"(a3), "r"(b0), "r"(b1));
}

__device__ __forceinline__ int swz(int row, int chunk) {
    return row * 128 + ((chunk ^ (row & 7)) << 3);
}

__global__ __launch_bounds__(256) void gemm_kernel(const float* __restrict__ bias,
                                                   float* __restrict__ out) {
    __shared__ __half sA[128 * 128];   // 32 KB
    __shared__ __half sB[64 * 128];    // 16 KB

    const int tid  = threadIdx.x;
    const int lane = tid & 31;
    const int wid  = tid >> 5;
    const int wm   = wid >> 1;
    const int wn   = wid & 1;
    const int m0   = blockIdx.x * 128;
    const int nb0  = blockIdx.y * 128;

    const int lq = lane >> 2;
    const int lr = lane & 3;
    const int r0 = tid >> 4;
    const int c  = tid & 15;

    #pragma unroll
    for (int it = 0; it < 8; ++it) {
        const int r = r0 + it * 16;
        const uint4 v = reinterpret_cast<const uint4*>(
            g_pooled_h + (size_t)(m0 + r) * EMB)[c];
        *reinterpret_cast<uint4*>(&sA[swz(r, c)]) = v;
    }

    #pragma unroll
    for (int p = 0; p < 2; ++p) {
        const int n0 = nb0 + p * 64;

        if (p) __syncthreads();
        #pragma unroll
        for (int it = 0; it < 4; ++it) {
            const int r = r0 + it * 16;
            uint4 v = make_uint4(0u, 0u, 0u, 0u);
            if (n0 + r < NCLS)
                v = reinterpret_cast<const uint4*>(g_w_h + (size_t)(n0 + r) * EMB)[c];
            *reinterpret_cast<uint4*>(&sB[swz(r, c)]) = v;
        }
        __syncthreads();

        float acc[2][4][4] = {};

        #pragma unroll
        for (int ks = 0; ks < 8; ++ks) {
            uint32_t a[2][4];
            #pragma unroll
            for (int mi = 0; mi < 2; ++mi) {
                const int r  = wm * 32 + mi * 16 + lq;
                const int o0 = ((2 * ks)     ^ (r & 7)) * 8 + lr * 2;
                const int o1 = ((2 * ks + 1) ^ (r & 7)) * 8 + lr * 2;
                a[mi][0] = *reinterpret_cast<const uint32_t*>(&sA[r * 128 + o0]);
                a[mi][1] = *reinterpret_cast<const uint32_t*>(&sA[(r + 8) * 128 + o0]);
                a[mi][2] = *reinterpret_cast<const uint32_t*>(&sA[r * 128 + o1]);
                a[mi][3] = *reinterpret_cast<const uint32_t*>(&sA[(r + 8) * 128 + o1]);
            }
            #pragma unroll
            for (int nt = 0; nt < 4; ++nt) {
                const int n  = wn * 32 + nt * 8 + lq;
                const int o0 = ((2 * ks)     ^ (n & 7)) * 8 + lr * 2;
                const int o1 = ((2 * ks + 1) ^ (n & 7)) * 8 + lr * 2;
                const uint32_t b0 = *reinterpret_cast<const uint32_t*>(&sB[n * 128 + o0]);
                const uint32_t b1 = *reinterpret_cast<const uint32_t*>(&sB[n * 128 + o1]);
                #pragma unroll
                for (int mi = 0; mi < 2; ++mi)
                    mma16816(acc[mi][nt], a[mi][0], a[mi][1], a[mi][2], a[mi][3], b0, b1);
            }
        }

        #pragma unroll
        for (int nt = 0; nt < 4; ++nt) {
            const int n = n0 + wn * 32 + nt * 8 + lr * 2;
            if (n < NCLS) {
                const float2 b2 = *reinterpret_cast<const float2*>(bias + n);
                #pragma unroll
                for (int mi = 0; mi < 2; ++mi) {
                    const int m = m0 + wm * 32 + mi * 16 + lq;
                    float2 s0, s1;
                    s0.x = acc[mi][nt][0] + b2.x;
                    s0.y = acc[mi][nt][1] + b2.y;
                    s1.x = acc[mi][nt][2] + b2.x;
                    s1.y = acc[mi][nt][3] + b2.y;
                    *reinterpret_cast<float2*>(out + (size_t)m * NCLS + n)       = s0;
                    *reinterpret_cast<float2*>(out + (size_t)(m + 8) * NCLS + n) = s1;
                }
            }
        }
    }
}

extern "C" void kernel_launch(void* const* d_in, const int* in_sizes, int n_in,
                              void* d_out, int out_size) {
    const int*   seq   = (const int*)d_in[0];
    const float* table = (const float*)d_in[1];
    const float* W     = (const float*)d_in[2];
    const float* bias  = (const float*)d_in[3];
    float*       out   = (float*)d_out;

    const int conv_blocks = (int)((N_ALL4 + 1023) / 1024);
    convert_kernel<<<conv_blocks, 256>>>(table, W);

    pool_kernel<<<NB / 8, 256>>>(seq);

    dim3 grid(NB / 128, (NCLS + 127) / 128);
    gemm_kernel<<<grid, 256>>>(bias, out);
}

// round 11
// speedup vs baseline: 1.0435x; 1.0162x over previous
#include <cuda_runtime.h>
#include <cuda_fp16.h>
#include <cstddef>
#include <cstdint>

#define VOCAB 100000
#define NB    16384
#define LSEQ  200
#define EMB   128
#define NCLS  1000

// fp16 table stored as TWO PLANES: plane h (h=0,1) holds fp16 elements
// [h*64, h*64+64) of every row, at plane stride VOCAB*64 halves (12.8 MB).
// This puts the two 128B halves of a row into different L2-hash groups
// (hash uses addr bits {8,10-27}; a 256B-contiguous row puts all 8 sectors
// on ONE LTS slice — an 8-deep per-slice burst and the suspected limiter).
#define PLANE_H  ((size_t)VOCAB * 64)     // plane stride in fp16 elements
#define PLANE_U2 ((size_t)VOCAB * 16)     // plane stride in uint2 (8B) units

// Scratch (alloc-free rule: __device__ globals).
__device__ __align__(16) __half g_table_h[2 * PLANE_H];           // 25.6 MB
__device__ __align__(16) __half g_w_h[(size_t)NCLS * EMB];        // 256 KB
__device__ __align__(16) __half g_pooled_h[(size_t)NB * EMB];     // 4 MB

// ---------------------------------------------------------------------------
// Stage 0: convert table AND fc_w fp32 -> fp16 (table into 2-plane layout).
// MLP_p1 = 4 structure (proven 12.2 us).
// ---------------------------------------------------------------------------
#define N_TBL4 ((size_t)VOCAB * EMB / 4)   // 3,200,000 float4 (32 per row)
#define N_W4   ((size_t)NCLS * EMB / 4)
#define N_ALL4 (N_TBL4 + N_W4)

__global__ __launch_bounds__(256) void convert_kernel(const float* __restrict__ t,
                                                      const float* __restrict__ W) {
    const size_t base = (size_t)blockIdx.x * 1024 + threadIdx.x;
    float4 v[4];
    bool   ok[4];
    #pragma unroll
    for (int i = 0; i < 4; ++i) {
        const size_t idx = base + (size_t)i * 256;
        ok[i] = idx < N_ALL4;
        if (ok[i])
            v[i] = (idx < N_TBL4) ? reinterpret_cast<const float4*>(t)[idx]
                                  : reinterpret_cast<const float4*>(W)[idx - N_TBL4];
    }
    #pragma unroll
    for (int i = 0; i < 4; ++i) {
        if (!ok[i]) continue;
        const size_t idx = base + (size_t)i * 256;
        union { __half2 h[2]; uint2 u; } pk;
        pk.h[0] = __floats2half2_rn(v[i].x, v[i].y);
        pk.h[1] = __floats2half2_rn(v[i].z, v[i].w);
        if (idx < N_TBL4) {
            // Source float4 idx -> row r, quarter-chunk q (32 float4 per row).
            const size_t r = idx >> 5;
            const int    q = (int)(idx & 31);
            // fp16 elements e = q*4..q*4+3; plane h = q>>4; within-plane (q&15).
            const size_t dst = (size_t)(q >> 4) * PLANE_U2 + r * 16 + (q & 15);
            reinterpret_cast<uint2*>(g_table_h)[dst] = pk.u;
        } else {
            reinterpret_cast<uint2*>(g_w_h)[idx - N_TBL4] = pk.u;
        }
    }
}

// ---------------------------------------------------------------------------
// Stage 1: masked embedding-bag sum pool — R3 structure, 2-plane gather.
// Lane covers fp16 elements lane*4..lane*4+3 exactly as before (the plane
// mapping (lane>>4)*64 + (lane&15)*4 == lane*4), so accumulation arithmetic
// and the pooled layout are bit-identical to the proven R3 pool.
// ---------------------------------------------------------------------------
__device__ __forceinline__ void hacc(float4& a, uint2 u) {
    const float2 f0 = __half22float2(*reinterpret_cast<__half2*>(&u.x));
    const float2 f1 = __half22float2(*reinterpret_cast<__half2*>(&u.y));
    a.x += f0.x; a.y += f0.y; a.z += f1.x; a.w += f1.y;
}

__global__ __launch_bounds__(256) void pool_kernel(const int* __restrict__ seq) {
    __shared__ int s_tok[8][LSEQ];
    const int wid  = threadIdx.x >> 5;
    const int lane = threadIdx.x & 31;
    const int b0   = blockIdx.x * 8;

    for (int i = threadIdx.x; i < 8 * LSEQ; i += 256)
        s_tok[i / LSEQ][i % LSEQ] = seq[(size_t)b0 * LSEQ + i];
    __syncthreads();

    // Per-lane base into the 2-plane table (uint2 units).
    const uint2* tbl = reinterpret_cast<const uint2*>(g_table_h)
                       + (size_t)(lane >> 4) * PLANE_U2 + (lane & 15);

    float4 a0 = {0,0,0,0}, a1 = {0,0,0,0}, a2 = {0,0,0,0}, a3 = {0,0,0,0};

    #pragma unroll 2
    for (int l = 0; l < LSEQ; l += 4) {
        const int t0 = s_tok[wid][l + 0];
        const int t1 = s_tok[wid][l + 1];
        const int t2 = s_tok[wid][l + 2];
        const int t3 = s_tok[wid][l + 3];
        if (t0) hacc(a0, tbl[(size_t)t0 * 16]);
        if (t1) hacc(a1, tbl[(size_t)t1 * 16]);
        if (t2) hacc(a2, tbl[(size_t)t2 * 16]);
        if (t3) hacc(a3, tbl[(size_t)t3 * 16]);
    }

    union { __half2 h[2]; uint2 u; } pk;
    pk.h[0] = __floats2half2_rn((a0.x + a1.x) + (a2.x + a3.x),
                                (a0.y + a1.y) + (a2.y + a3.y));
    pk.h[1] = __floats2half2_rn((a0.z + a1.z) + (a2.z + a3.z),
                                (a0.w + a1.w) + (a2.w + a3.w));
    reinterpret_cast<uint2*>(g_pooled_h + (size_t)(b0 + wid) * EMB)[lane] = pk.u;
}

// ---------------------------------------------------------------------------
// Stage 2: HMMA GEMM — EXACT R7 version (proven).
// ---------------------------------------------------------------------------
__device__ __forceinline__ void mma16816(float* d,
                                         uint32_t a0, uint32_t a1, uint32_t a2, uint32_t a3,
                                         uint32_t b0, uint32_t b1) {
    asm volatile(
        "mma.sync.aligned.m16n8k16.row.col.f32.f16.f16.f32 "
        "{%0,%1,%2,%3}, {%4,%5,%6,%7}, {%8,%9}, {%0,%1,%2,%3};\n"
        : "+f"(d[0]), "+f"(d[1]), "+f"(d[2]), "+f"(d[3])
        : "r"(a0), "r"(a1), "r"(a2), "r"(a3), "r"(b0), "r"(b1));
}

__device__ __forceinline__ int swz(int row, int chunk) {
    return row * 128 + ((chunk ^ (row & 7)) << 3);
}

__global__ __launch_bounds__(256) void gemm_kernel(const float* __restrict__ bias,
                                                   float* __restrict__ out) {
    __shared__ __half sA[128 * 128];   // 32 KB
    __shared__ __half sB[64 * 128];    // 16 KB

    const int tid  = threadIdx.x;
    const int lane = tid & 31;
    const int wid  = tid >> 5;
    const int wm   = wid >> 1;
    const int wn   = wid & 1;
    const int m0   = blockIdx.x * 128;
    const int nb0  = blockIdx.y * 128;

    const int lq = lane >> 2;
    const int lr = lane & 3;
    const int r0 = tid >> 4;
    const int c  = tid & 15;

    #pragma unroll
    for (int it = 0; it < 8; ++it) {
        const int r = r0 + it * 16;
        const uint4 v = reinterpret_cast<const uint4*>(
            g_pooled_h + (size_t)(m0 + r) * EMB)[c];
        *reinterpret_cast<uint4*>(&sA[swz(r, c)]) = v;
    }

    #pragma unroll
    for (int p = 0; p < 2; ++p) {
        const int n0 = nb0 + p * 64;

        if (p) __syncthreads();
        #pragma unroll
        for (int it = 0; it < 4; ++it) {
            const int r = r0 + it * 16;
            uint4 v = make_uint4(0u, 0u, 0u, 0u);
            if (n0 + r < NCLS)
                v = reinterpret_cast<const uint4*>(g_w_h + (size_t)(n0 + r) * EMB)[c];
            *reinterpret_cast<uint4*>(&sB[swz(r, c)]) = v;
        }
        __syncthreads();

        float acc[2][4][4] = {};

        #pragma unroll
        for (int ks = 0; ks < 8; ++ks) {
            uint32_t a[2][4];
            #pragma unroll
            for (int mi = 0; mi < 2; ++mi) {
                const int r  = wm * 32 + mi * 16 + lq;
                const int o0 = ((2 * ks)     ^ (r & 7)) * 8 + lr * 2;
                const int o1 = ((2 * ks + 1) ^ (r & 7)) * 8 + lr * 2;
                a[mi][0] = *reinterpret_cast<const uint32_t*>(&sA[r * 128 + o0]);
                a[mi][1] = *reinterpret_cast<const uint32_t*>(&sA[(r + 8) * 128 + o0]);
                a[mi][2] = *reinterpret_cast<const uint32_t*>(&sA[r * 128 + o1]);
                a[mi][3] = *reinterpret_cast<const uint32_t*>(&sA[(r + 8) * 128 + o1]);
            }
            #pragma unroll
            for (int nt = 0; nt < 4; ++nt) {
                const int n  = wn * 32 + nt * 8 + lq;
                const int o0 = ((2 * ks)     ^ (n & 7)) * 8 + lr * 2;
                const int o1 = ((2 * ks + 1) ^ (n & 7)) * 8 + lr * 2;
                const uint32_t b0 = *reinterpret_cast<const uint32_t*>(&sB[n * 128 + o0]);
                const uint32_t b1 = *reinterpret_cast<const uint32_t*>(&sB[n * 128 + o1]);
                #pragma unroll
                for (int mi = 0; mi < 2; ++mi)
                    mma16816(acc[mi][nt], a[mi][0], a[mi][1], a[mi][2], a[mi][3], b0, b1);
            }
        }

        #pragma unroll
        for (int nt = 0; nt < 4; ++nt) {
            const int n = n0 + wn * 32 + nt * 8 + lr * 2;
            if (n < NCLS) {
                const float2 b2 = *reinterpret_cast<const float2*>(bias + n);
                #pragma unroll
                for (int mi = 0; mi < 2; ++mi) {
                    const int m = m0 + wm * 32 + mi * 16 + lq;
                    float2 s0, s1;
                    s0.x = acc[mi][nt][0] + b2.x;
                    s0.y = acc[mi][nt][1] + b2.y;
                    s1.x = acc[mi][nt][2] + b2.x;
                    s1.y = acc[mi][nt][3] + b2.y;
                    *reinterpret_cast<float2*>(out + (size_t)m * NCLS + n)       = s0;
                    *reinterpret_cast<float2*>(out + (size_t)(m + 8) * NCLS + n) = s1;
                }
            }
        }
    }
}

extern "C" void kernel_launch(void* const* d_in, const int* in_sizes, int n_in,
                              void* d_out, int out_size) {
    const int*   seq   = (const int*)d_in[0];
    const float* table = (const float*)d_in[1];
    const float* W     = (const float*)d_in[2];
    const float* bias  = (const float*)d_in[3];
    float*       out   = (float*)d_out;

    const int conv_blocks = (int)((N_ALL4 + 1023) / 1024);
    convert_kernel<<<conv_blocks, 256>>>(table, W);

    pool_kernel<<<NB / 8, 256>>>(seq);

    dim3 grid(NB / 128, (NCLS + 127) / 128);
    gemm_kernel<<<grid, 256>>>(bias, out);
}